// round 4
// baseline (speedup 1.0000x reference)
#include <cuda_runtime.h>
#include <math.h>

#define BATCH 4
#define SEQ   1024
#define HID   1024
#define NH    16
#define HDIM  64

// Scratch (allocation-free rule: __device__ globals)
__device__ float g_Q[BATCH * SEQ * HID];
__device__ float g_K[BATCH * SEQ * HID];
__device__ float g_V[BATCH * SEQ * HID];
__device__ float g_A[BATCH * SEQ * HID];

// ---------------------------------------------------------------------------
// SGEMM: C[M,N] = A[M,K] @ B[K,N] + bias[N]
// 128x128 block tile, BK=8, 8x8 thread tile, 256 threads, smem double buffer.
// M=4096, N=1024, K=1024 -> all tile-divisible, no bounds checks.
// ---------------------------------------------------------------------------
__global__ __launch_bounds__(256) void sgemm_bias(
    const float* __restrict__ A, const float* __restrict__ Bm,
    const float* __restrict__ bias, float* __restrict__ C,
    int M, int N, int K)
{
    constexpr int BM = 128, BN = 128, BK = 8, TM = 8, TN = 8;
    __shared__ float As[2][BK][BM];
    __shared__ float Bs[2][BK][BN];

    const int tid = threadIdx.x;
    const int tx = (tid % 16) * TN;   // output col within tile
    const int ty = (tid / 16) * TM;   // output row within tile

    const int aRow = tid >> 1;          // 0..127
    const int aCol = (tid & 1) * 4;     // 0 or 4
    const int bRow = tid >> 5;          // 0..7
    const int bCol = (tid & 31) * 4;    // 0..124

    const float* Ab = A + (size_t)(blockIdx.y * BM) * K;
    const float* Bb = Bm + (size_t)(blockIdx.x * BN);

    float acc[TM][TN];
    #pragma unroll
    for (int i = 0; i < TM; i++)
        #pragma unroll
        for (int j = 0; j < TN; j++) acc[i][j] = 0.0f;

    // preload tile 0
    float4 a4 = *reinterpret_cast<const float4*>(Ab + (size_t)aRow * K + aCol);
    float4 b4 = *reinterpret_cast<const float4*>(Bb + (size_t)bRow * N + bCol);
    As[0][aCol + 0][aRow] = a4.x;
    As[0][aCol + 1][aRow] = a4.y;
    As[0][aCol + 2][aRow] = a4.z;
    As[0][aCol + 3][aRow] = a4.w;
    *reinterpret_cast<float4*>(&Bs[0][bRow][bCol]) = b4;
    __syncthreads();

    const int ntiles = K / BK;
    for (int t = 0; t < ntiles; t++) {
        const int cur = t & 1;
        if (t + 1 < ntiles) {
            a4 = *reinterpret_cast<const float4*>(Ab + (size_t)aRow * K + (t + 1) * BK + aCol);
            b4 = *reinterpret_cast<const float4*>(Bb + (size_t)((t + 1) * BK + bRow) * N + bCol);
        }
        #pragma unroll
        for (int kk = 0; kk < BK; kk++) {
            float ar[TM], br[TN];
            #pragma unroll
            for (int i = 0; i < TM; i++) ar[i] = As[cur][kk][ty + i];
            #pragma unroll
            for (int j = 0; j < TN; j++) br[j] = Bs[cur][kk][tx + j];
            #pragma unroll
            for (int i = 0; i < TM; i++)
                #pragma unroll
                for (int j = 0; j < TN; j++)
                    acc[i][j] = fmaf(ar[i], br[j], acc[i][j]);
        }
        if (t + 1 < ntiles) {
            const int nxt = cur ^ 1;
            As[nxt][aCol + 0][aRow] = a4.x;
            As[nxt][aCol + 1][aRow] = a4.y;
            As[nxt][aCol + 2][aRow] = a4.z;
            As[nxt][aCol + 3][aRow] = a4.w;
            *reinterpret_cast<float4*>(&Bs[nxt][bRow][bCol]) = b4;
            __syncthreads();
        }
    }

    const float* bptr = bias + blockIdx.x * BN + tx;
    float* Cb = C + (size_t)(blockIdx.y * BM + ty) * N + blockIdx.x * BN + tx;
    #pragma unroll
    for (int i = 0; i < TM; i++) {
        #pragma unroll
        for (int j = 0; j < TN; j += 4) {
            float4 o;
            o.x = acc[i][j + 0] + bptr[j + 0];
            o.y = acc[i][j + 1] + bptr[j + 1];
            o.z = acc[i][j + 2] + bptr[j + 2];
            o.w = acc[i][j + 3] + bptr[j + 3];
            *reinterpret_cast<float4*>(Cb + (size_t)i * N + j) = o;
        }
    }
}

// ---------------------------------------------------------------------------
// Flash attention (fp32). One CTA per (b, h, 64-query tile). 256 threads.
// Thread (tidy 0..15, tidx 0..15): queries q = tidy*4+i, keys k = tidx+16j.
// smem: sQt[64][65] | union{ sK[128][65], sP[64][129] } | sV[128][64]
// = 20672 floats = 82688 bytes -> 2 CTAs/SM.
// Q/K/V layout: [B, seq, H*HD] row-major; head h at column offset h*64.
// Softmax scale 1/sqrt(1024)=1/32 folded into Q on smem load.
// ---------------------------------------------------------------------------
#define FLASH_SMEM_FLOATS (64 * 65 + 128 * 65 + 128 * 64)

__global__ __launch_bounds__(256) void flash_attn(
    const float* __restrict__ Q, const float* __restrict__ K,
    const float* __restrict__ V, float* __restrict__ O)
{
    extern __shared__ float sm[];
    float* sQt = sm;                   // [d][q], stride 65
    float* sKP = sm + 64 * 65;         // sK: [k][d] stride 65 / sP: [q][k] stride 129
    float* sV  = sKP + 128 * 65;       // [k][d], stride 64

    const int tid  = threadIdx.x;
    const int tidx = tid & 15;
    const int tidy = tid >> 4;
    const int qt = blockIdx.x;         // 0..15
    const int h  = blockIdx.y;         // 0..15
    const int b  = blockIdx.z;         // 0..3

    const size_t rowQ0 = (size_t)(b * SEQ + qt * 64);
    const size_t rowK0 = (size_t)(b * SEQ);
    const size_t colh  = (size_t)h * HDIM;
    const int d4 = tidx * 4;

    // load Q tile (transposed, pre-scaled)
    const float inv_scale = 1.0f / 32.0f;
    #pragma unroll
    for (int p = 0; p < 4; p++) {
        const int q = p * 16 + tidy;
        float4 v4 = *reinterpret_cast<const float4*>(Q + (rowQ0 + q) * HID + colh + d4);
        sQt[(d4 + 0) * 65 + q] = v4.x * inv_scale;
        sQt[(d4 + 1) * 65 + q] = v4.y * inv_scale;
        sQt[(d4 + 2) * 65 + q] = v4.z * inv_scale;
        sQt[(d4 + 3) * 65 + q] = v4.w * inv_scale;
    }

    float mrow[4], lrow[4], acc[4][4];
    #pragma unroll
    for (int i = 0; i < 4; i++) {
        mrow[i] = -1e30f;
        lrow[i] = 0.0f;
        #pragma unroll
        for (int j = 0; j < 4; j++) acc[i][j] = 0.0f;
    }

    for (int kt = 0; kt < 8; kt++) {
        __syncthreads();  // prior PV done (and Q stores visible on first iter)
        // load K (transposed-free [k][d]) and V tiles
        #pragma unroll
        for (int p = 0; p < 8; p++) {
            const int krel = p * 16 + tidy;
            const size_t g = (rowK0 + (size_t)kt * 128 + krel) * HID + colh + d4;
            float4 k4 = *reinterpret_cast<const float4*>(K + g);
            sKP[krel * 65 + d4 + 0] = k4.x;
            sKP[krel * 65 + d4 + 1] = k4.y;
            sKP[krel * 65 + d4 + 2] = k4.z;
            sKP[krel * 65 + d4 + 3] = k4.w;
            float4 v4 = *reinterpret_cast<const float4*>(V + g);
            *reinterpret_cast<float4*>(&sV[krel * 64 + d4]) = v4;
        }
        __syncthreads();

        // S = Q K^T  (4 queries x 8 keys per thread)
        float s[4][8];
        #pragma unroll
        for (int i = 0; i < 4; i++)
            #pragma unroll
            for (int j = 0; j < 8; j++) s[i][j] = 0.0f;

        #pragma unroll 4
        for (int d = 0; d < 64; d++) {
            const float a0 = sQt[d * 65 + tidy * 4 + 0];
            const float a1 = sQt[d * 65 + tidy * 4 + 1];
            const float a2 = sQt[d * 65 + tidy * 4 + 2];
            const float a3 = sQt[d * 65 + tidy * 4 + 3];
            #pragma unroll
            for (int j = 0; j < 8; j++) {
                const float bk = sKP[(tidx + 16 * j) * 65 + d];
                s[0][j] = fmaf(a0, bk, s[0][j]);
                s[1][j] = fmaf(a1, bk, s[1][j]);
                s[2][j] = fmaf(a2, bk, s[2][j]);
                s[3][j] = fmaf(a3, bk, s[3][j]);
            }
        }
        __syncthreads();  // all K reads done before P overwrites the union

        // online softmax update + write P
        #pragma unroll
        for (int i = 0; i < 4; i++) {
            float tmax = s[i][0];
            #pragma unroll
            for (int j = 1; j < 8; j++) tmax = fmaxf(tmax, s[i][j]);
            #pragma unroll
            for (int off = 8; off >= 1; off >>= 1)
                tmax = fmaxf(tmax, __shfl_xor_sync(0xffffffffu, tmax, off));
            const float mn = fmaxf(mrow[i], tmax);
            const float alpha = __expf(mrow[i] - mn);
            float rs = 0.0f;
            #pragma unroll
            for (int j = 0; j < 8; j++) {
                const float p = __expf(s[i][j] - mn);
                s[i][j] = p;
                rs += p;
            }
            #pragma unroll
            for (int off = 8; off >= 1; off >>= 1)
                rs += __shfl_xor_sync(0xffffffffu, rs, off);
            lrow[i] = lrow[i] * alpha + rs;
            mrow[i] = mn;
            acc[i][0] *= alpha; acc[i][1] *= alpha;
            acc[i][2] *= alpha; acc[i][3] *= alpha;
            #pragma unroll
            for (int j = 0; j < 8; j++)
                sKP[(tidy * 4 + i) * 129 + tidx + 16 * j] = s[i][j];
        }
        __syncthreads();  // P visible

        // O += P @ V  (each thread: 4 queries x 4 dims at d = tidx*4..+3)
        #pragma unroll 4
        for (int k = 0; k < 128; k++) {
            const float4 vv = *reinterpret_cast<const float4*>(&sV[k * 64 + d4]);
            #pragma unroll
            for (int i = 0; i < 4; i++) {
                const float p = sKP[(tidy * 4 + i) * 129 + k];
                acc[i][0] = fmaf(p, vv.x, acc[i][0]);
                acc[i][1] = fmaf(p, vv.y, acc[i][1]);
                acc[i][2] = fmaf(p, vv.z, acc[i][2]);
                acc[i][3] = fmaf(p, vv.w, acc[i][3]);
            }
        }
    }

    // epilogue: O / l
    #pragma unroll
    for (int i = 0; i < 4; i++) {
        const float invl = 1.0f / lrow[i];
        const int q = tidy * 4 + i;
        float4 o;
        o.x = acc[i][0] * invl;
        o.y = acc[i][1] * invl;
        o.z = acc[i][2] * invl;
        o.w = acc[i][3] * invl;
        *reinterpret_cast<float4*>(O + (rowQ0 + q) * HID + colh + d4) = o;
    }
}

// ---------------------------------------------------------------------------
extern "C" void kernel_launch(void* const* d_in, const int* in_sizes, int n_in,
                              void* d_out, int out_size)
{
    const float* vh = (const float*)d_in[0];  // v_hidden_states [4,1024,1024]
    const float* lh = (const float*)d_in[1];  // l_hidden_states [4,1024,1024]
    const float* qw = (const float*)d_in[2];
    const float* qb = (const float*)d_in[3];
    const float* kw = (const float*)d_in[4];
    const float* kb = (const float*)d_in[5];
    const float* vw = (const float*)d_in[6];
    const float* vb = (const float*)d_in[7];
    const float* ow = (const float*)d_in[8];
    const float* ob = (const float*)d_in[9];
    float* out = (float*)d_out;

    float *Qp, *Kp, *Vp, *Ap;
    cudaGetSymbolAddress((void**)&Qp, g_Q);
    cudaGetSymbolAddress((void**)&Kp, g_K);
    cudaGetSymbolAddress((void**)&Vp, g_V);
    cudaGetSymbolAddress((void**)&Ap, g_A);

    const int M = BATCH * SEQ;  // 4096
    const int N = HID;          // 1024
    const int Kd = HID;         // 1024
    dim3 ggrid(N / 128, M / 128);  // (8, 32)

    // QKV projections
    sgemm_bias<<<ggrid, 256>>>(lh, qw, qb, Qp, M, N, Kd);
    sgemm_bias<<<ggrid, 256>>>(vh, kw, kb, Kp, M, N, Kd);
    sgemm_bias<<<ggrid, 256>>>(vh, vw, vb, Vp, M, N, Kd);

    // attention
    const int smem_bytes = FLASH_SMEM_FLOATS * (int)sizeof(float);
    cudaFuncSetAttribute(flash_attn, cudaFuncAttributeMaxDynamicSharedMemorySize,
                         smem_bytes);
    flash_attn<<<dim3(SEQ / 64, NH, BATCH), 256, smem_bytes>>>(Qp, Kp, Vp, Ap);

    // output projection -> d_out
    sgemm_bias<<<ggrid, 256>>>(Ap, ow, ob, out, M, N, Kd);
}

// round 10
// speedup vs baseline: 1.5283x; 1.5283x over previous
#include <cuda_runtime.h>
#include <cuda_bf16.h>
#include <math.h>
#include <stdint.h>

#define BATCH 4
#define SEQ   1024
#define HID   1024
#define NH    16
#define HDIM  64

// ---------------------------------------------------------------------------
// Scratch (allocation-free rule: __device__ globals)
// ---------------------------------------------------------------------------
__device__ float g_Q[BATCH * SEQ * HID];
__device__ float g_K[BATCH * SEQ * HID];
__device__ float g_V[BATCH * SEQ * HID];
__device__ float g_A[BATCH * SEQ * HID];
// transposed + hi/lo-split weights: 4 x [N=1024][K=1024] bf16 (q,k,v,o)
__device__ __nv_bfloat16 g_W_hi[4][HID * HID];
__device__ __nv_bfloat16 g_W_lo[4][HID * HID];

// ---------------------------------------------------------------------------
// Helpers (plain sm_90-class PTX only: ldmatrix + mma.sync — no tcgen05)
// ---------------------------------------------------------------------------
__device__ __forceinline__ uint32_t smem_u32(const void* p) {
    return (uint32_t)__cvta_generic_to_shared(p);
}
__device__ __forceinline__ void ldsm4(uint32_t r[4], uint32_t addr) {
    asm volatile("ldmatrix.sync.aligned.m8n8.x4.shared.b16 {%0,%1,%2,%3}, [%4];"
                 : "=r"(r[0]), "=r"(r[1]), "=r"(r[2]), "=r"(r[3]) : "r"(addr));
}
__device__ __forceinline__ void mma_bf16(float c[4], const uint32_t a[4],
                                         uint32_t b0, uint32_t b1) {
    asm volatile(
        "mma.sync.aligned.m16n8k16.row.col.f32.bf16.bf16.f32 "
        "{%0,%1,%2,%3}, {%4,%5,%6,%7}, {%8,%9}, {%0,%1,%2,%3};"
        : "+f"(c[0]), "+f"(c[1]), "+f"(c[2]), "+f"(c[3])
        : "r"(a[0]), "r"(a[1]), "r"(a[2]), "r"(a[3]), "r"(b0), "r"(b1));
}
// fp32x4 -> 4 bf16 hi (uint2) + 4 bf16 lo (uint2), lo = rn(x - hi)
__device__ __forceinline__ void split4(float4 x, uint2& hi, uint2& lo) {
    __nv_bfloat162 h0 = __floats2bfloat162_rn(x.x, x.y);
    __nv_bfloat162 h1 = __floats2bfloat162_rn(x.z, x.w);
    float2 f0 = __bfloat1622float2(h0);
    float2 f1 = __bfloat1622float2(h1);
    __nv_bfloat162 l0 = __floats2bfloat162_rn(x.x - f0.x, x.y - f0.y);
    __nv_bfloat162 l1 = __floats2bfloat162_rn(x.z - f1.x, x.w - f1.y);
    hi.x = *reinterpret_cast<uint32_t*>(&h0);
    hi.y = *reinterpret_cast<uint32_t*>(&h1);
    lo.x = *reinterpret_cast<uint32_t*>(&l0);
    lo.y = *reinterpret_cast<uint32_t*>(&l1);
}

// ---------------------------------------------------------------------------
// Weight prep: W[K,N] fp32 -> WT_hi/WT_lo [N,K] bf16 (transpose + split)
// ---------------------------------------------------------------------------
__global__ __launch_bounds__(256) void wprep(
    const float* __restrict__ W,
    __nv_bfloat16* __restrict__ WT_hi, __nv_bfloat16* __restrict__ WT_lo)
{
    __shared__ float t[32][33];
    const int tx = threadIdx.x, ty = threadIdx.y;
    const int nb = blockIdx.x * 32, kb = blockIdx.y * 32;
    #pragma unroll
    for (int r = 0; r < 4; r++)
        t[ty + r * 8][tx] = W[(size_t)(kb + ty + r * 8) * HID + nb + tx];
    __syncthreads();
    #pragma unroll
    for (int r = 0; r < 4; r++) {
        const int n = nb + ty + r * 8;
        const int k = kb + tx;
        const float x = t[tx][ty + r * 8];
        __nv_bfloat16 h = __float2bfloat16(x);
        WT_hi[(size_t)n * HID + k] = h;
        WT_lo[(size_t)n * HID + k] = __float2bfloat16(x - __bfloat162float(h));
    }
}

// ---------------------------------------------------------------------------
// mma.sync bf16 GEMM with 3-term compensation:
//   C[4096,1024] = A[4096,1024] @ W + bias   (W given as W^T hi/lo, [N][K])
// CTA tile 128x128, BK=32, 256 threads = 8 warps (2m x 4n), warp tile 64x32.
// smem per stage: Ahi | Alo | Bhi | Blo, each 128 rows x 80 bytes (pad +16B).
// ---------------------------------------------------------------------------
#define G_TILE  10240            // 128 * 80 bytes
#define G_STAGE (4 * G_TILE)     // 40960
#define G_SMEM  (2 * G_STAGE)    // 81920

extern __shared__ char dyn_smem[];

__global__ __launch_bounds__(256, 1) void gemm_mma(
    const float* __restrict__ A,
    const __nv_bfloat16* __restrict__ BhT,
    const __nv_bfloat16* __restrict__ BlT,
    const float* __restrict__ bias,
    float* __restrict__ C)
{
    char* smg = dyn_smem;
    const uint32_t sb = smem_u32(smg);
    const int tid = threadIdx.x;
    const int lane = tid & 31, wid = tid >> 5;
    const int wm = wid >> 2, wn = wid & 3;      // warp grid 2 x 4
    const int bn = blockIdx.x, bm = blockIdx.y;

    const float* Ag = A + (size_t)bm * 128 * HID;
    const __nv_bfloat16* Bh = BhT + (size_t)bn * 128 * HID;
    const __nv_bfloat16* Bl = BlT + (size_t)bn * 128 * HID;

    float acc[4][4][4];
    #pragma unroll
    for (int i = 0; i < 4; i++)
        #pragma unroll
        for (int j = 0; j < 4; j++)
            #pragma unroll
            for (int r = 0; r < 4; r++) acc[i][j][r] = 0.0f;

    const int arow = tid >> 3, aq = tid & 7;    // A: 8 float4 per 32-float row
    const int brow = tid >> 2, bq = tid & 3;    // B: 4 uint4 per 32-bf16 row

    float4 aR[4];
    uint4 bhR[2], blR[2];

    // ---- preload tile 0 into regs ----
    #pragma unroll
    for (int i = 0; i < 4; i++)
        aR[i] = *reinterpret_cast<const float4*>(
            Ag + (size_t)(arow + i * 32) * HID + aq * 4);
    #pragma unroll
    for (int i = 0; i < 2; i++) {
        const int n = brow + i * 64;
        bhR[i] = *reinterpret_cast<const uint4*>(Bh + (size_t)n * HID + bq * 8);
        blR[i] = *reinterpret_cast<const uint4*>(Bl + (size_t)n * HID + bq * 8);
    }
    // ---- store stage 0 ----
    {
        char* st = smg;
        #pragma unroll
        for (int i = 0; i < 4; i++) {
            uint2 hi, lo;
            split4(aR[i], hi, lo);
            const int row = arow + i * 32;
            *reinterpret_cast<uint2*>(st + row * 80 + aq * 8) = hi;
            *reinterpret_cast<uint2*>(st + G_TILE + row * 80 + aq * 8) = lo;
        }
        #pragma unroll
        for (int i = 0; i < 2; i++) {
            const int n = brow + i * 64;
            *reinterpret_cast<uint4*>(st + 2 * G_TILE + n * 80 + bq * 16) = bhR[i];
            *reinterpret_cast<uint4*>(st + 3 * G_TILE + n * 80 + bq * 16) = blR[i];
        }
    }
    __syncthreads();

    const int r16 = lane & 15, hs = lane >> 4;
    const int NT = HID / 32;   // 32 k-iterations

    for (int t = 0; t < NT; t++) {
        const int buf = t & 1;
        // issue next tile's global loads before compute (latency overlap)
        if (t + 1 < NT) {
            const int kc = (t + 1) * 32;
            #pragma unroll
            for (int i = 0; i < 4; i++)
                aR[i] = *reinterpret_cast<const float4*>(
                    Ag + (size_t)(arow + i * 32) * HID + kc + aq * 4);
            #pragma unroll
            for (int i = 0; i < 2; i++) {
                const int n = brow + i * 64;
                bhR[i] = *reinterpret_cast<const uint4*>(
                    Bh + (size_t)n * HID + kc + bq * 8);
                blR[i] = *reinterpret_cast<const uint4*>(
                    Bl + (size_t)n * HID + kc + bq * 8);
            }
        }

        // ---- compute on smem[buf] ----
        const uint32_t s0 = sb + buf * G_STAGE;
        #pragma unroll
        for (int ks = 0; ks < 2; ks++) {
            const uint32_t koff = ks * 32 + hs * 16;
            uint32_t ah[4][4], al[4][4];
            #pragma unroll
            for (int mt = 0; mt < 4; mt++) {
                const uint32_t ad = s0 + (wm * 64 + mt * 16 + r16) * 80 + koff;
                ldsm4(ah[mt], ad);
                ldsm4(al[mt], ad + G_TILE);
            }
            uint32_t bh[2][4], bl[2][4];
            #pragma unroll
            for (int p = 0; p < 2; p++) {
                const uint32_t bd =
                    s0 + 2 * G_TILE + (wn * 32 + p * 16 + r16) * 80 + koff;
                ldsm4(bh[p], bd);
                ldsm4(bl[p], bd + G_TILE);
            }
            #pragma unroll
            for (int mt = 0; mt < 4; mt++)
                #pragma unroll
                for (int nt = 0; nt < 4; nt++) {
                    const int p = nt >> 1, s = nt & 1;
                    mma_bf16(acc[mt][nt], ah[mt], bh[p][s], bh[p][s + 2]);
                    mma_bf16(acc[mt][nt], al[mt], bh[p][s], bh[p][s + 2]);
                    mma_bf16(acc[mt][nt], ah[mt], bl[p][s], bl[p][s + 2]);
                }
        }

        // ---- store next tile into the other buffer ----
        if (t + 1 < NT) {
            char* st = smg + (buf ^ 1) * G_STAGE;
            #pragma unroll
            for (int i = 0; i < 4; i++) {
                uint2 hi, lo;
                split4(aR[i], hi, lo);
                const int row = arow + i * 32;
                *reinterpret_cast<uint2*>(st + row * 80 + aq * 8) = hi;
                *reinterpret_cast<uint2*>(st + G_TILE + row * 80 + aq * 8) = lo;
            }
            #pragma unroll
            for (int i = 0; i < 2; i++) {
                const int n = brow + i * 64;
                *reinterpret_cast<uint4*>(st + 2 * G_TILE + n * 80 + bq * 16) = bhR[i];
                *reinterpret_cast<uint4*>(st + 3 * G_TILE + n * 80 + bq * 16) = blR[i];
            }
            __syncthreads();
        }
    }

    // ---- epilogue: bias + store ----
    #pragma unroll
    for (int mt = 0; mt < 4; mt++) {
        const int row = bm * 128 + wm * 64 + mt * 16 + (lane >> 2);
        #pragma unroll
        for (int nt = 0; nt < 4; nt++) {
            const int col = bn * 128 + wn * 32 + nt * 8 + (lane & 3) * 2;
            const float2 bb = *reinterpret_cast<const float2*>(bias + col);
            float2 o0, o1;
            o0.x = acc[mt][nt][0] + bb.x;
            o0.y = acc[mt][nt][1] + bb.y;
            o1.x = acc[mt][nt][2] + bb.x;
            o1.y = acc[mt][nt][3] + bb.y;
            *reinterpret_cast<float2*>(C + (size_t)row * HID + col) = o0;
            *reinterpret_cast<float2*>(C + (size_t)(row + 8) * HID + col) = o1;
        }
    }
}

// ---------------------------------------------------------------------------
// Flash attention (fp32) — unchanged from R4 (passing, 493us).
// ---------------------------------------------------------------------------
#define FLASH_SMEM_FLOATS (64 * 65 + 128 * 65 + 128 * 64)

__global__ __launch_bounds__(256) void flash_attn(
    const float* __restrict__ Q, const float* __restrict__ K,
    const float* __restrict__ V, float* __restrict__ O)
{
    float* smf = reinterpret_cast<float*>(dyn_smem);
    float* sQt = smf;
    float* sKP = smf + 64 * 65;
    float* sV  = sKP + 128 * 65;

    const int tid  = threadIdx.x;
    const int tidx = tid & 15;
    const int tidy = tid >> 4;
    const int qt = blockIdx.x;
    const int h  = blockIdx.y;
    const int b  = blockIdx.z;

    const size_t rowQ0 = (size_t)(b * SEQ + qt * 64);
    const size_t rowK0 = (size_t)(b * SEQ);
    const size_t colh  = (size_t)h * HDIM;
    const int d4 = tidx * 4;

    const float inv_scale = 1.0f / 32.0f;
    #pragma unroll
    for (int p = 0; p < 4; p++) {
        const int q = p * 16 + tidy;
        float4 v4 = *reinterpret_cast<const float4*>(Q + (rowQ0 + q) * HID + colh + d4);
        sQt[(d4 + 0) * 65 + q] = v4.x * inv_scale;
        sQt[(d4 + 1) * 65 + q] = v4.y * inv_scale;
        sQt[(d4 + 2) * 65 + q] = v4.z * inv_scale;
        sQt[(d4 + 3) * 65 + q] = v4.w * inv_scale;
    }

    float mrow[4], lrow[4], acc[4][4];
    #pragma unroll
    for (int i = 0; i < 4; i++) {
        mrow[i] = -1e30f;
        lrow[i] = 0.0f;
        #pragma unroll
        for (int j = 0; j < 4; j++) acc[i][j] = 0.0f;
    }

    for (int kt = 0; kt < 8; kt++) {
        __syncthreads();
        #pragma unroll
        for (int p = 0; p < 8; p++) {
            const int krel = p * 16 + tidy;
            const size_t g = (rowK0 + (size_t)kt * 128 + krel) * HID + colh + d4;
            float4 k4 = *reinterpret_cast<const float4*>(K + g);
            sKP[krel * 65 + d4 + 0] = k4.x;
            sKP[krel * 65 + d4 + 1] = k4.y;
            sKP[krel * 65 + d4 + 2] = k4.z;
            sKP[krel * 65 + d4 + 3] = k4.w;
            float4 v4 = *reinterpret_cast<const float4*>(V + g);
            *reinterpret_cast<float4*>(&sV[krel * 64 + d4]) = v4;
        }
        __syncthreads();

        float s[4][8];
        #pragma unroll
        for (int i = 0; i < 4; i++)
            #pragma unroll
            for (int j = 0; j < 8; j++) s[i][j] = 0.0f;

        #pragma unroll 4
        for (int d = 0; d < 64; d++) {
            const float a0 = sQt[d * 65 + tidy * 4 + 0];
            const float a1 = sQt[d * 65 + tidy * 4 + 1];
            const float a2 = sQt[d * 65 + tidy * 4 + 2];
            const float a3 = sQt[d * 65 + tidy * 4 + 3];
            #pragma unroll
            for (int j = 0; j < 8; j++) {
                const float bk = sKP[(tidx + 16 * j) * 65 + d];
                s[0][j] = fmaf(a0, bk, s[0][j]);
                s[1][j] = fmaf(a1, bk, s[1][j]);
                s[2][j] = fmaf(a2, bk, s[2][j]);
                s[3][j] = fmaf(a3, bk, s[3][j]);
            }
        }
        __syncthreads();

        #pragma unroll
        for (int i = 0; i < 4; i++) {
            float tmax = s[i][0];
            #pragma unroll
            for (int j = 1; j < 8; j++) tmax = fmaxf(tmax, s[i][j]);
            #pragma unroll
            for (int off = 8; off >= 1; off >>= 1)
                tmax = fmaxf(tmax, __shfl_xor_sync(0xffffffffu, tmax, off));
            const float mn = fmaxf(mrow[i], tmax);
            const float alpha = __expf(mrow[i] - mn);
            float rs = 0.0f;
            #pragma unroll
            for (int j = 0; j < 8; j++) {
                const float p = __expf(s[i][j] - mn);
                s[i][j] = p;
                rs += p;
            }
            #pragma unroll
            for (int off = 8; off >= 1; off >>= 1)
                rs += __shfl_xor_sync(0xffffffffu, rs, off);
            lrow[i] = lrow[i] * alpha + rs;
            mrow[i] = mn;
            acc[i][0] *= alpha; acc[i][1] *= alpha;
            acc[i][2] *= alpha; acc[i][3] *= alpha;
            #pragma unroll
            for (int j = 0; j < 8; j++)
                sKP[(tidy * 4 + i) * 129 + tidx + 16 * j] = s[i][j];
        }
        __syncthreads();

        #pragma unroll 4
        for (int k = 0; k < 128; k++) {
            const float4 vv = *reinterpret_cast<const float4*>(&sV[k * 64 + d4]);
            #pragma unroll
            for (int i = 0; i < 4; i++) {
                const float p = sKP[(tidy * 4 + i) * 129 + k];
                acc[i][0] = fmaf(p, vv.x, acc[i][0]);
                acc[i][1] = fmaf(p, vv.y, acc[i][1]);
                acc[i][2] = fmaf(p, vv.z, acc[i][2]);
                acc[i][3] = fmaf(p, vv.w, acc[i][3]);
            }
        }
    }

    #pragma unroll
    for (int i = 0; i < 4; i++) {
        const float invl = 1.0f / lrow[i];
        const int q = tidy * 4 + i;
        float4 o;
        o.x = acc[i][0] * invl;
        o.y = acc[i][1] * invl;
        o.z = acc[i][2] * invl;
        o.w = acc[i][3] * invl;
        *reinterpret_cast<float4*>(O + (rowQ0 + q) * HID + colh + d4) = o;
    }
}

// ---------------------------------------------------------------------------
extern "C" void kernel_launch(void* const* d_in, const int* in_sizes, int n_in,
                              void* d_out, int out_size)
{
    const float* vh = (const float*)d_in[0];
    const float* lh = (const float*)d_in[1];
    const float* qw = (const float*)d_in[2];
    const float* qb = (const float*)d_in[3];
    const float* kw = (const float*)d_in[4];
    const float* kb = (const float*)d_in[5];
    const float* vw = (const float*)d_in[6];
    const float* vb = (const float*)d_in[7];
    const float* ow = (const float*)d_in[8];
    const float* ob = (const float*)d_in[9];
    float* out = (float*)d_out;

    float *Qp, *Kp, *Vp, *Ap;
    cudaGetSymbolAddress((void**)&Qp, g_Q);
    cudaGetSymbolAddress((void**)&Kp, g_K);
    cudaGetSymbolAddress((void**)&Vp, g_V);
    cudaGetSymbolAddress((void**)&Ap, g_A);
    __nv_bfloat16 *WH, *WL;
    cudaGetSymbolAddress((void**)&WH, g_W_hi);
    cudaGetSymbolAddress((void**)&WL, g_W_lo);
    const size_t WSZ = (size_t)HID * HID;

    // weight prep: transpose + bf16 hi/lo split
    dim3 pg(HID / 32, HID / 32), pb(32, 8);
    wprep<<<pg, pb>>>(qw, WH + 0 * WSZ, WL + 0 * WSZ);
    wprep<<<pg, pb>>>(kw, WH + 1 * WSZ, WL + 1 * WSZ);
    wprep<<<pg, pb>>>(vw, WH + 2 * WSZ, WL + 2 * WSZ);
    wprep<<<pg, pb>>>(ow, WH + 3 * WSZ, WL + 3 * WSZ);

    cudaFuncSetAttribute(gemm_mma, cudaFuncAttributeMaxDynamicSharedMemorySize,
                         G_SMEM);
    dim3 ggrid(HID / 128, (BATCH * SEQ) / 128);  // (8, 32)

    gemm_mma<<<ggrid, 256, G_SMEM>>>(lh, WH + 0 * WSZ, WL + 0 * WSZ, qb, Qp);
    gemm_mma<<<ggrid, 256, G_SMEM>>>(vh, WH + 1 * WSZ, WL + 1 * WSZ, kb, Kp);
    gemm_mma<<<ggrid, 256, G_SMEM>>>(vh, WH + 2 * WSZ, WL + 2 * WSZ, vb, Vp);

    const int smem_bytes = FLASH_SMEM_FLOATS * (int)sizeof(float);
    cudaFuncSetAttribute(flash_attn, cudaFuncAttributeMaxDynamicSharedMemorySize,
                         smem_bytes);
    flash_attn<<<dim3(SEQ / 64, NH, BATCH), 256, smem_bytes>>>(Qp, Kp, Vp, Ap);

    gemm_mma<<<ggrid, 256, G_SMEM>>>(Ap, WH + 3 * WSZ, WL + 3 * WSZ, ob, out);
}

// round 12
// speedup vs baseline: 2.4121x; 1.5783x over previous
#include <cuda_runtime.h>
#include <cuda_bf16.h>
#include <math.h>
#include <stdint.h>

#define BATCH 4
#define SEQ   1024
#define HID   1024
#define NH    16
#define HDIM  64

// ---------------------------------------------------------------------------
// Scratch (allocation-free rule: __device__ globals)
// ---------------------------------------------------------------------------
__device__ float g_Q[BATCH * SEQ * HID];
__device__ float g_K[BATCH * SEQ * HID];
__device__ float g_V[BATCH * SEQ * HID];
__device__ float g_A[BATCH * SEQ * HID];
// transposed + hi/lo-split weights: 4 x [N=1024][K=1024] bf16 (q,k,v,o)
__device__ __nv_bfloat16 g_W_hi[4][HID * HID];
__device__ __nv_bfloat16 g_W_lo[4][HID * HID];

// ---------------------------------------------------------------------------
// Helpers (plain sm_90-class PTX only: ldmatrix + mma.sync — no tcgen05)
// ---------------------------------------------------------------------------
__device__ __forceinline__ uint32_t smem_u32(const void* p) {
    return (uint32_t)__cvta_generic_to_shared(p);
}
__device__ __forceinline__ void ldsm4(uint32_t r[4], uint32_t addr) {
    asm volatile("ldmatrix.sync.aligned.m8n8.x4.shared.b16 {%0,%1,%2,%3}, [%4];"
                 : "=r"(r[0]), "=r"(r[1]), "=r"(r[2]), "=r"(r[3]) : "r"(addr));
}
__device__ __forceinline__ void ldsm4t(uint32_t r[4], uint32_t addr) {
    asm volatile("ldmatrix.sync.aligned.m8n8.x4.trans.shared.b16 {%0,%1,%2,%3}, [%4];"
                 : "=r"(r[0]), "=r"(r[1]), "=r"(r[2]), "=r"(r[3]) : "r"(addr));
}
__device__ __forceinline__ void mma_bf16(float c[4], const uint32_t a[4],
                                         uint32_t b0, uint32_t b1) {
    asm volatile(
        "mma.sync.aligned.m16n8k16.row.col.f32.bf16.bf16.f32 "
        "{%0,%1,%2,%3}, {%4,%5,%6,%7}, {%8,%9}, {%0,%1,%2,%3};"
        : "+f"(c[0]), "+f"(c[1]), "+f"(c[2]), "+f"(c[3])
        : "r"(a[0]), "r"(a[1]), "r"(a[2]), "r"(a[3]), "r"(b0), "r"(b1));
}
// fp32x4 -> 4 bf16 hi (uint2) + 4 bf16 lo (uint2), lo = rn(x - hi)
__device__ __forceinline__ void split4(float4 x, uint2& hi, uint2& lo) {
    __nv_bfloat162 h0 = __floats2bfloat162_rn(x.x, x.y);
    __nv_bfloat162 h1 = __floats2bfloat162_rn(x.z, x.w);
    float2 f0 = __bfloat1622float2(h0);
    float2 f1 = __bfloat1622float2(h1);
    __nv_bfloat162 l0 = __floats2bfloat162_rn(x.x - f0.x, x.y - f0.y);
    __nv_bfloat162 l1 = __floats2bfloat162_rn(x.z - f1.x, x.w - f1.y);
    hi.x = *reinterpret_cast<uint32_t*>(&h0);
    hi.y = *reinterpret_cast<uint32_t*>(&h1);
    lo.x = *reinterpret_cast<uint32_t*>(&l0);
    lo.y = *reinterpret_cast<uint32_t*>(&l1);
}
// pack two fp32 -> bf16x2 hi, return hi, write residual lo
__device__ __forceinline__ uint32_t pack2(float x, float y, uint32_t& lo) {
    __nv_bfloat162 h = __floats2bfloat162_rn(x, y);
    float2 f = __bfloat1622float2(h);
    __nv_bfloat162 l = __floats2bfloat162_rn(x - f.x, y - f.y);
    lo = *reinterpret_cast<uint32_t*>(&l);
    return *reinterpret_cast<uint32_t*>(&h);
}

// ---------------------------------------------------------------------------
// Weight prep: W[K,N] fp32 -> WT_hi/WT_lo [N,K] bf16 (transpose + split)
// ---------------------------------------------------------------------------
__global__ __launch_bounds__(256) void wprep(
    const float* __restrict__ W,
    __nv_bfloat16* __restrict__ WT_hi, __nv_bfloat16* __restrict__ WT_lo)
{
    __shared__ float t[32][33];
    const int tx = threadIdx.x, ty = threadIdx.y;
    const int nb = blockIdx.x * 32, kb = blockIdx.y * 32;
    #pragma unroll
    for (int r = 0; r < 4; r++)
        t[ty + r * 8][tx] = W[(size_t)(kb + ty + r * 8) * HID + nb + tx];
    __syncthreads();
    #pragma unroll
    for (int r = 0; r < 4; r++) {
        const int n = nb + ty + r * 8;
        const int k = kb + tx;
        const float x = t[tx][ty + r * 8];
        __nv_bfloat16 h = __float2bfloat16(x);
        WT_hi[(size_t)n * HID + k] = h;
        WT_lo[(size_t)n * HID + k] = __float2bfloat16(x - __bfloat162float(h));
    }
}

// ---------------------------------------------------------------------------
// mma.sync bf16 GEMM with 3-term compensation (unchanged from R10, passing)
// ---------------------------------------------------------------------------
#define G_TILE  10240            // 128 * 80 bytes
#define G_STAGE (4 * G_TILE)     // 40960
#define G_SMEM  (2 * G_STAGE)    // 81920

extern __shared__ char dyn_smem[];

__global__ __launch_bounds__(256, 1) void gemm_mma(
    const float* __restrict__ A,
    const __nv_bfloat16* __restrict__ BhT,
    const __nv_bfloat16* __restrict__ BlT,
    const float* __restrict__ bias,
    float* __restrict__ C)
{
    char* smg = dyn_smem;
    const uint32_t sb = smem_u32(smg);
    const int tid = threadIdx.x;
    const int lane = tid & 31, wid = tid >> 5;
    const int wm = wid >> 2, wn = wid & 3;      // warp grid 2 x 4
    const int bn = blockIdx.x, bm = blockIdx.y;

    const float* Ag = A + (size_t)bm * 128 * HID;
    const __nv_bfloat16* Bh = BhT + (size_t)bn * 128 * HID;
    const __nv_bfloat16* Bl = BlT + (size_t)bn * 128 * HID;

    float acc[4][4][4];
    #pragma unroll
    for (int i = 0; i < 4; i++)
        #pragma unroll
        for (int j = 0; j < 4; j++)
            #pragma unroll
            for (int r = 0; r < 4; r++) acc[i][j][r] = 0.0f;

    const int arow = tid >> 3, aq = tid & 7;
    const int brow = tid >> 2, bq = tid & 3;

    float4 aR[4];
    uint4 bhR[2], blR[2];

    #pragma unroll
    for (int i = 0; i < 4; i++)
        aR[i] = *reinterpret_cast<const float4*>(
            Ag + (size_t)(arow + i * 32) * HID + aq * 4);
    #pragma unroll
    for (int i = 0; i < 2; i++) {
        const int n = brow + i * 64;
        bhR[i] = *reinterpret_cast<const uint4*>(Bh + (size_t)n * HID + bq * 8);
        blR[i] = *reinterpret_cast<const uint4*>(Bl + (size_t)n * HID + bq * 8);
    }
    {
        char* st = smg;
        #pragma unroll
        for (int i = 0; i < 4; i++) {
            uint2 hi, lo;
            split4(aR[i], hi, lo);
            const int row = arow + i * 32;
            *reinterpret_cast<uint2*>(st + row * 80 + aq * 8) = hi;
            *reinterpret_cast<uint2*>(st + G_TILE + row * 80 + aq * 8) = lo;
        }
        #pragma unroll
        for (int i = 0; i < 2; i++) {
            const int n = brow + i * 64;
            *reinterpret_cast<uint4*>(st + 2 * G_TILE + n * 80 + bq * 16) = bhR[i];
            *reinterpret_cast<uint4*>(st + 3 * G_TILE + n * 80 + bq * 16) = blR[i];
        }
    }
    __syncthreads();

    const int r16 = lane & 15, hs = lane >> 4;
    const int NT = HID / 32;

    for (int t = 0; t < NT; t++) {
        const int buf = t & 1;
        if (t + 1 < NT) {
            const int kc = (t + 1) * 32;
            #pragma unroll
            for (int i = 0; i < 4; i++)
                aR[i] = *reinterpret_cast<const float4*>(
                    Ag + (size_t)(arow + i * 32) * HID + kc + aq * 4);
            #pragma unroll
            for (int i = 0; i < 2; i++) {
                const int n = brow + i * 64;
                bhR[i] = *reinterpret_cast<const uint4*>(
                    Bh + (size_t)n * HID + kc + bq * 8);
                blR[i] = *reinterpret_cast<const uint4*>(
                    Bl + (size_t)n * HID + kc + bq * 8);
            }
        }

        const uint32_t s0 = sb + buf * G_STAGE;
        #pragma unroll
        for (int ks = 0; ks < 2; ks++) {
            const uint32_t koff = ks * 32 + hs * 16;
            uint32_t ah[4][4], al[4][4];
            #pragma unroll
            for (int mt = 0; mt < 4; mt++) {
                const uint32_t ad = s0 + (wm * 64 + mt * 16 + r16) * 80 + koff;
                ldsm4(ah[mt], ad);
                ldsm4(al[mt], ad + G_TILE);
            }
            uint32_t bh[2][4], bl[2][4];
            #pragma unroll
            for (int p = 0; p < 2; p++) {
                const uint32_t bd =
                    s0 + 2 * G_TILE + (wn * 32 + p * 16 + r16) * 80 + koff;
                ldsm4(bh[p], bd);
                ldsm4(bl[p], bd + G_TILE);
            }
            #pragma unroll
            for (int mt = 0; mt < 4; mt++)
                #pragma unroll
                for (int nt = 0; nt < 4; nt++) {
                    const int p = nt >> 1, s = nt & 1;
                    mma_bf16(acc[mt][nt], ah[mt], bh[p][s], bh[p][s + 2]);
                    mma_bf16(acc[mt][nt], al[mt], bh[p][s], bh[p][s + 2]);
                    mma_bf16(acc[mt][nt], ah[mt], bl[p][s], bl[p][s + 2]);
                }
        }

        if (t + 1 < NT) {
            char* st = smg + (buf ^ 1) * G_STAGE;
            #pragma unroll
            for (int i = 0; i < 4; i++) {
                uint2 hi, lo;
                split4(aR[i], hi, lo);
                const int row = arow + i * 32;
                *reinterpret_cast<uint2*>(st + row * 80 + aq * 8) = hi;
                *reinterpret_cast<uint2*>(st + G_TILE + row * 80 + aq * 8) = lo;
            }
            #pragma unroll
            for (int i = 0; i < 2; i++) {
                const int n = brow + i * 64;
                *reinterpret_cast<uint4*>(st + 2 * G_TILE + n * 80 + bq * 16) = bhR[i];
                *reinterpret_cast<uint4*>(st + 3 * G_TILE + n * 80 + bq * 16) = blR[i];
            }
            __syncthreads();
        }
    }

    #pragma unroll
    for (int mt = 0; mt < 4; mt++) {
        const int row = bm * 128 + wm * 64 + mt * 16 + (lane >> 2);
        #pragma unroll
        for (int nt = 0; nt < 4; nt++) {
            const int col = bn * 128 + wn * 32 + nt * 8 + (lane & 3) * 2;
            const float2 bb = *reinterpret_cast<const float2*>(bias + col);
            float2 o0, o1;
            o0.x = acc[mt][nt][0] + bb.x;
            o0.y = acc[mt][nt][1] + bb.y;
            o1.x = acc[mt][nt][2] + bb.x;
            o1.y = acc[mt][nt][3] + bb.y;
            *reinterpret_cast<float2*>(C + (size_t)row * HID + col) = o0;
            *reinterpret_cast<float2*>(C + (size_t)(row + 8) * HID + col) = o1;
        }
    }
}

// ---------------------------------------------------------------------------
// Flash attention via mma.sync bf16 + 3-term compensation.
// CTA: 64 queries x 1 head. 128 threads = 4 warps, warp = 16 query rows.
// Key tiles of 128. K/V split hi/lo in smem (144B padded rows).
// Q A-fragments held in registers for the whole kernel.
// P stays in registers (S C-fragment layout == PV A-fragment layout).
// ---------------------------------------------------------------------------
#define F_ROWB 144
#define F_TILE (128 * F_ROWB)      // 18432
#define F_SMEM (4 * F_TILE)        // 73728: Khi | Klo | Vhi | Vlo

__global__ __launch_bounds__(128, 2) void flash_mma(
    const float* __restrict__ Q, const float* __restrict__ K,
    const float* __restrict__ V, float* __restrict__ O)
{
    char* smg = dyn_smem;
    const uint32_t sb = smem_u32(smg);
    const int tid = threadIdx.x, lane = tid & 31, wid = tid >> 5;
    const int qt = blockIdx.x, h = blockIdx.y, b = blockIdx.z;
    const size_t qbase = (size_t)(b * SEQ + qt * 64);
    const size_t kbase = (size_t)(b * SEQ);
    const int colh = h * HDIM;

    // ---- prologue: stage scaled Q (64x64) hi/lo into K buffers ----
    {
        const int r0 = tid >> 4, q = tid & 15;
        #pragma unroll
        for (int p = 0; p < 8; p++) {
            const int row = r0 + p * 8;
            float4 x = *reinterpret_cast<const float4*>(
                Q + (qbase + row) * HID + colh + q * 4);
            x.x *= 0.03125f; x.y *= 0.03125f; x.z *= 0.03125f; x.w *= 0.03125f;
            uint2 hi, lo;
            split4(x, hi, lo);
            *reinterpret_cast<uint2*>(smg + row * F_ROWB + q * 8) = hi;
            *reinterpret_cast<uint2*>(smg + F_TILE + row * F_ROWB + q * 8) = lo;
        }
    }
    __syncthreads();
    // Q A-fragments: rows wid*16..+15, 4 k-steps of 16
    uint32_t qh[4][4], ql[4][4];
    {
        const uint32_t base = sb + (wid * 16 + (lane & 15)) * F_ROWB + (lane >> 4) * 16;
        #pragma unroll
        for (int ks = 0; ks < 4; ks++) {
            ldsm4(qh[ks], base + ks * 32);
            ldsm4(ql[ks], base + ks * 32 + F_TILE);
        }
    }
    __syncthreads();

    float m0 = -1e30f, m1 = -1e30f, l0 = 0.0f, l1 = 0.0f;
    float oacc[8][4];
    #pragma unroll
    for (int j = 0; j < 8; j++)
        #pragma unroll
        for (int r = 0; r < 4; r++) oacc[j][r] = 0.0f;

    for (int kt = 0; kt < 8; kt++) {
        if (kt) __syncthreads();
        // ---- load K/V tile (128 x 64), split hi/lo into smem ----
        {
            const int r0 = tid >> 4, q = tid & 15;
            #pragma unroll
            for (int p = 0; p < 16; p++) {
                const int row = r0 + p * 8;
                const size_t g = (kbase + (size_t)kt * 128 + row) * HID + colh + q * 4;
                uint2 hi, lo;
                split4(*reinterpret_cast<const float4*>(K + g), hi, lo);
                *reinterpret_cast<uint2*>(smg + row * F_ROWB + q * 8) = hi;
                *reinterpret_cast<uint2*>(smg + F_TILE + row * F_ROWB + q * 8) = lo;
                split4(*reinterpret_cast<const float4*>(V + g), hi, lo);
                *reinterpret_cast<uint2*>(smg + 2 * F_TILE + row * F_ROWB + q * 8) = hi;
                *reinterpret_cast<uint2*>(smg + 3 * F_TILE + row * F_ROWB + q * 8) = lo;
            }
        }
        __syncthreads();

        // ---- S = Q K^T (16 n-tiles of 8 keys) ----
        float sacc[16][4];
        #pragma unroll
        for (int j = 0; j < 16; j++)
            #pragma unroll
            for (int r = 0; r < 4; r++) sacc[j][r] = 0.0f;

        #pragma unroll
        for (int ks = 0; ks < 4; ks++) {
            const uint32_t koff = ks * 32 + (lane >> 4) * 16;
            #pragma unroll
            for (int kg = 0; kg < 8; kg++) {
                uint32_t bh[4], bl[4];
                const uint32_t bd = sb + (kg * 16 + (lane & 15)) * F_ROWB + koff;
                ldsm4(bh, bd);
                ldsm4(bl, bd + F_TILE);
                mma_bf16(sacc[2 * kg],     qh[ks], bh[0], bh[2]);
                mma_bf16(sacc[2 * kg],     ql[ks], bh[0], bh[2]);
                mma_bf16(sacc[2 * kg],     qh[ks], bl[0], bl[2]);
                mma_bf16(sacc[2 * kg + 1], qh[ks], bh[1], bh[3]);
                mma_bf16(sacc[2 * kg + 1], ql[ks], bh[1], bh[3]);
                mma_bf16(sacc[2 * kg + 1], qh[ks], bl[1], bl[3]);
            }
        }

        // ---- online softmax (rows r = lane>>2 and r+8; quad-reduce) ----
        float tm0 = -1e30f, tm1 = -1e30f;
        #pragma unroll
        for (int j = 0; j < 16; j++) {
            tm0 = fmaxf(tm0, fmaxf(sacc[j][0], sacc[j][1]));
            tm1 = fmaxf(tm1, fmaxf(sacc[j][2], sacc[j][3]));
        }
        tm0 = fmaxf(tm0, __shfl_xor_sync(0xffffffffu, tm0, 1));
        tm0 = fmaxf(tm0, __shfl_xor_sync(0xffffffffu, tm0, 2));
        tm1 = fmaxf(tm1, __shfl_xor_sync(0xffffffffu, tm1, 1));
        tm1 = fmaxf(tm1, __shfl_xor_sync(0xffffffffu, tm1, 2));
        const float nm0 = fmaxf(m0, tm0), nm1 = fmaxf(m1, tm1);
        const float a0 = __expf(m0 - nm0), a1 = __expf(m1 - nm1);
        float rs0 = 0.0f, rs1 = 0.0f;
        #pragma unroll
        for (int j = 0; j < 16; j++) {
            sacc[j][0] = __expf(sacc[j][0] - nm0);
            sacc[j][1] = __expf(sacc[j][1] - nm0);
            sacc[j][2] = __expf(sacc[j][2] - nm1);
            sacc[j][3] = __expf(sacc[j][3] - nm1);
            rs0 += sacc[j][0] + sacc[j][1];
            rs1 += sacc[j][2] + sacc[j][3];
        }
        rs0 += __shfl_xor_sync(0xffffffffu, rs0, 1);
        rs0 += __shfl_xor_sync(0xffffffffu, rs0, 2);
        rs1 += __shfl_xor_sync(0xffffffffu, rs1, 1);
        rs1 += __shfl_xor_sync(0xffffffffu, rs1, 2);
        l0 = l0 * a0 + rs0;
        l1 = l1 * a1 + rs1;
        m0 = nm0; m1 = nm1;
        #pragma unroll
        for (int j = 0; j < 8; j++) {
            oacc[j][0] *= a0; oacc[j][1] *= a0;
            oacc[j][2] *= a1; oacc[j][3] *= a1;
        }

        // ---- O += P V (P from registers, V via ldmatrix.trans) ----
        #pragma unroll
        for (int ks = 0; ks < 8; ks++) {
            uint32_t ah[4], al[4];
            ah[0] = pack2(sacc[2 * ks][0],     sacc[2 * ks][1],     al[0]);
            ah[1] = pack2(sacc[2 * ks][2],     sacc[2 * ks][3],     al[1]);
            ah[2] = pack2(sacc[2 * ks + 1][0], sacc[2 * ks + 1][1], al[2]);
            ah[3] = pack2(sacc[2 * ks + 1][2], sacc[2 * ks + 1][3], al[3]);
            const uint32_t vbase =
                sb + 2 * F_TILE + (ks * 16 + (lane & 15)) * F_ROWB + (lane >> 4) * 16;
            #pragma unroll
            for (int j = 0; j < 4; j++) {
                uint32_t vh[4], vl[4];
                ldsm4t(vh, vbase + j * 32);
                ldsm4t(vl, vbase + j * 32 + F_TILE);
                mma_bf16(oacc[2 * j],     ah, vh[0], vh[1]);
                mma_bf16(oacc[2 * j],     al, vh[0], vh[1]);
                mma_bf16(oacc[2 * j],     ah, vl[0], vl[1]);
                mma_bf16(oacc[2 * j + 1], ah, vh[2], vh[3]);
                mma_bf16(oacc[2 * j + 1], al, vh[2], vh[3]);
                mma_bf16(oacc[2 * j + 1], ah, vl[2], vl[3]);
            }
        }
    }

    // ---- epilogue: O / l ----
    const float il0 = 1.0f / l0, il1 = 1.0f / l1;
    const int r = lane >> 2;
    const size_t row0 = qbase + wid * 16 + r;
    #pragma unroll
    for (int j = 0; j < 8; j++) {
        const int col = colh + j * 8 + (lane & 3) * 2;
        float2 o0, o1;
        o0.x = oacc[j][0] * il0; o0.y = oacc[j][1] * il0;
        o1.x = oacc[j][2] * il1; o1.y = oacc[j][3] * il1;
        *reinterpret_cast<float2*>(O + row0 * HID + col) = o0;
        *reinterpret_cast<float2*>(O + (row0 + 8) * HID + col) = o1;
    }
}

// ---------------------------------------------------------------------------
extern "C" void kernel_launch(void* const* d_in, const int* in_sizes, int n_in,
                              void* d_out, int out_size)
{
    const float* vh = (const float*)d_in[0];
    const float* lh = (const float*)d_in[1];
    const float* qw = (const float*)d_in[2];
    const float* qb = (const float*)d_in[3];
    const float* kw = (const float*)d_in[4];
    const float* kb = (const float*)d_in[5];
    const float* vw = (const float*)d_in[6];
    const float* vb = (const float*)d_in[7];
    const float* ow = (const float*)d_in[8];
    const float* ob = (const float*)d_in[9];
    float* out = (float*)d_out;

    float *Qp, *Kp, *Vp, *Ap;
    cudaGetSymbolAddress((void**)&Qp, g_Q);
    cudaGetSymbolAddress((void**)&Kp, g_K);
    cudaGetSymbolAddress((void**)&Vp, g_V);
    cudaGetSymbolAddress((void**)&Ap, g_A);
    __nv_bfloat16 *WH, *WL;
    cudaGetSymbolAddress((void**)&WH, g_W_hi);
    cudaGetSymbolAddress((void**)&WL, g_W_lo);
    const size_t WSZ = (size_t)HID * HID;

    // weight prep: transpose + bf16 hi/lo split
    dim3 pg(HID / 32, HID / 32), pb(32, 8);
    wprep<<<pg, pb>>>(qw, WH + 0 * WSZ, WL + 0 * WSZ);
    wprep<<<pg, pb>>>(kw, WH + 1 * WSZ, WL + 1 * WSZ);
    wprep<<<pg, pb>>>(vw, WH + 2 * WSZ, WL + 2 * WSZ);
    wprep<<<pg, pb>>>(ow, WH + 3 * WSZ, WL + 3 * WSZ);

    cudaFuncSetAttribute(gemm_mma, cudaFuncAttributeMaxDynamicSharedMemorySize,
                         G_SMEM);
    dim3 ggrid(HID / 128, (BATCH * SEQ) / 128);  // (8, 32)

    gemm_mma<<<ggrid, 256, G_SMEM>>>(lh, WH + 0 * WSZ, WL + 0 * WSZ, qb, Qp);
    gemm_mma<<<ggrid, 256, G_SMEM>>>(vh, WH + 1 * WSZ, WL + 1 * WSZ, kb, Kp);
    gemm_mma<<<ggrid, 256, G_SMEM>>>(vh, WH + 2 * WSZ, WL + 2 * WSZ, vb, Vp);

    cudaFuncSetAttribute(flash_mma, cudaFuncAttributeMaxDynamicSharedMemorySize,
                         F_SMEM);
    flash_mma<<<dim3(SEQ / 64, NH, BATCH), 128, F_SMEM>>>(Qp, Kp, Vp, Ap);

    gemm_mma<<<ggrid, 256, G_SMEM>>>(Ap, WH + 3 * WSZ, WL + 3 * WSZ, ob, out);
}